// round 13
// baseline (speedup 1.0000x reference)
#include <cuda_runtime.h>
#include <cuda_fp16.h>
#include <stdint.h>

// SplineConv: N=100000, E=1.6M, DIM=2, K=5, deg-1 open spline, M_in=M_out=32, K_TOT=25.
#define MAXN 100000
#define MAXE 1600000
#define KTOT 25
#define KM   800    // KTOT*32 Z-channels per node

// ---------------- device scratch (allocation-free) ----------------
__device__ __half g_Zh[(size_t)MAXN * KM];   // 160 MB fp16 Z[n, p]  (p = k*32+o)
__device__ __half g_Wh[KTOT * 32 * 32];      // [p=800][i=32] f16  (B operand)
__device__ uint2  g_edesc2[MAXE];            // row-sorted 8B descriptors {col|kidx<<20, fx16|fy16<<16}
__device__ int    g_histN[MAXN + 1];
__device__ int    g_startN[MAXN + 1];        // CSR offsets
__device__ int    g_offN[MAXN + 1];          // scatter cursors
__device__ int    g_bsum[256];
__device__ int    g_bpre[256];
__device__ int    g_is64;

__device__ __forceinline__ uint32_t smem_u32(const void* p) {
    uint32_t a;
    asm("{ .reg .u64 t; cvta.to.shared.u64 t, %1; cvt.u32.u64 %0, t; }" : "=r"(a) : "l"(p));
    return a;
}
__device__ __forceinline__ void ldsm_x4(uint32_t addr, uint32_t* r) {
    asm volatile("ldmatrix.sync.aligned.m8n8.x4.shared.b16 {%0,%1,%2,%3}, [%4];"
        : "=r"(r[0]), "=r"(r[1]), "=r"(r[2]), "=r"(r[3]) : "r"(addr));
}
__device__ __forceinline__ void mma16816(float* d, const uint32_t* a, uint32_t b0, uint32_t b1) {
    asm volatile("mma.sync.aligned.m16n8k16.row.col.f32.f16.f16.f32 "
        "{%0,%1,%2,%3}, {%4,%5,%6,%7}, {%8,%9}, {%0,%1,%2,%3};"
        : "+f"(d[0]), "+f"(d[1]), "+f"(d[2]), "+f"(d[3])
        : "r"(a[0]), "r"(a[1]), "r"(a[2]), "r"(a[3]), "r"(b0), "r"(b1));
}
__device__ __forceinline__ uint32_t packh2(float lo, float hi) {
    uint32_t r;
    asm("cvt.rn.f16x2.f32 %0, %1, %2;" : "=r"(r) : "f"(hi), "f"(lo));
    return r;
}

// ---------------- dtype detection + histogram zero ----------------
__global__ void k_detect(const unsigned int* __restrict__ w, int nwords) {
    __shared__ int nz;
    if (threadIdx.x == 0) nz = 0;
    __syncthreads();
    int lim = nwords < 4096 ? nwords : 4096;
    int any = 0;
    for (int i = 1 + 2 * (int)threadIdx.x; i < lim; i += 2 * (int)blockDim.x)
        if (w[i] != 0u) any = 1;
    if (any) atomicOr(&nz, 1);
    __syncthreads();
    if (threadIdx.x == 0) g_is64 = (nz == 0) ? 1 : 0;
}

__global__ void k_zeroh(int N1) {
    int i = blockIdx.x * blockDim.x + threadIdx.x;
    if (i < N1) g_histN[i] = 0;
}

// ---------------- per-node degree histogram (100k spread atomics) ----------------
__global__ __launch_bounds__(256)
void k_hist(const void* __restrict__ ei, int E) {
    int e = blockIdx.x * blockDim.x + threadIdx.x;
    if (e >= E) return;
    int r;
    if (g_is64) r = (int)((const long long*)ei)[e];
    else        r = ((const int*)ei)[e];
    atomicAdd(&g_histN[r], 1);
}

// ---------------- multi-block scan (A: block sums, B: scan sums, C: local scan) ----------------
__global__ void kA_bsum(int N1) {
    __shared__ int ws[32];
    int t = threadIdx.x;
    int i = blockIdx.x * 1024 + t;
    int v = (i < N1) ? g_histN[i] : 0;
    for (int o = 16; o > 0; o >>= 1) v += __shfl_down_sync(0xffffffffu, v, o);
    if ((t & 31) == 0) ws[t >> 5] = v;
    __syncthreads();
    if (t < 32) {
        int s = ws[t];
        for (int o = 16; o > 0; o >>= 1) s += __shfl_down_sync(0xffffffffu, s, o);
        if (t == 0) g_bsum[blockIdx.x] = s;
    }
}
__global__ void kB_scan(int nsb) {
    __shared__ int ws[8];
    int t = threadIdx.x;
    int v = (t < nsb) ? g_bsum[t] : 0;
    int lane = t & 31, wid = t >> 5;
    int s = v;
    for (int o = 1; o < 32; o <<= 1) {
        int u = __shfl_up_sync(0xffffffffu, s, o);
        if (lane >= o) s += u;
    }
    if (lane == 31) ws[wid] = s;
    __syncthreads();
    if (wid == 0 && lane < 8) {
        int x2 = ws[lane];
        for (int o = 1; o < 8; o <<= 1) {
            int u = __shfl_up_sync(0xffu, x2, o);
            if (lane >= o) x2 += u;
        }
        ws[lane] = x2;
    }
    __syncthreads();
    int incl = s + (wid > 0 ? ws[wid - 1] : 0);
    if (t < nsb) g_bpre[t] = incl - v;
}
__global__ void kC_scan(int N1) {
    __shared__ int ws[32];
    int t = threadIdx.x;
    int i = blockIdx.x * 1024 + t;
    int v = (i < N1) ? g_histN[i] : 0;
    int lane = t & 31, wid = t >> 5;
    int s = v;
    for (int o = 1; o < 32; o <<= 1) {
        int u = __shfl_up_sync(0xffffffffu, s, o);
        if (lane >= o) s += u;
    }
    if (lane == 31) ws[wid] = s;
    __syncthreads();
    if (wid == 0) {
        int x2 = ws[lane];
        for (int o = 1; o < 32; o <<= 1) {
            int u = __shfl_up_sync(0xffffffffu, x2, o);
            if (lane >= o) x2 += u;
        }
        ws[lane] = x2;
    }
    __syncthreads();
    int excl = s - v + (wid > 0 ? ws[wid - 1] : 0) + g_bpre[blockIdx.x];
    if (i < N1) { g_startN[i] = excl; g_offN[i] = excl; }
}

// ---------------- scatter: compute 8B descriptor, counting-sort by row ----------------
__global__ __launch_bounds__(256)
void k_scatter(const void* __restrict__ ei, const float* __restrict__ pseudo, int E) {
    int e = blockIdx.x * blockDim.x + threadIdx.x;
    if (e >= E) return;
    int r, c;
    if (g_is64) {
        const long long* p = (const long long*)ei;
        r = (int)p[e]; c = (int)p[(size_t)E + e];
    } else {
        const int* p = (const int*)ei;
        r = p[e]; c = p[E + e];
    }
    float2 ps = ((const float2*)pseudo)[e];
    float px = ps.x * 4.0f, py = ps.y * 4.0f;   // scale = K-1 (open spline)
    float lx = fminf(fmaxf(floorf(px), 0.0f), 3.0f);
    float ly = fminf(fmaxf(floorf(py), 0.0f), 3.0f);
    int kidx = (int)ly * 5 + (int)lx;           // 0..18
    uint32_t fxu = (uint32_t)((px - lx) * 65535.0f + 0.5f);
    uint32_t fyu = (uint32_t)((py - ly) * 65535.0f + 0.5f);
    int pos = atomicAdd(&g_offN[r], 1);         // 100k spread cursors
    g_edesc2[pos] = make_uint2((uint32_t)c | ((uint32_t)kidx << 20),
                               fxu | (fyu << 16));
}

// ---------------- W transpose+convert: g_Wh[p][i] = W[k,i,o], p=k*32+o ----------------
__global__ void k_prep(const float* __restrict__ w) {
    int t = blockIdx.x * blockDim.x + threadIdx.x;
    if (t >= KTOT * 1024) return;
    int p = t >> 5, i = t & 31;
    int k = p >> 5, o = p & 31;
    g_Wh[t] = __float2half(w[k * 1024 + i * 32 + o]);
}

// ---------------- Z = x @ Wt via mma.sync m16n8k16, split-N over gridDim.y ----------------
#define NB_COLS 400
#define SB_OFF  10240                    // A: 128*80
#define ZG_SMEM (10240 + NB_COLS * 80)   // + B: 400*80 = 42240

__global__ __launch_bounds__(256, 4)
void k_zgemm_mma(const float* __restrict__ x, int N) {
    extern __shared__ __align__(128) char smem[];
    char* sA = smem;
    char* sB = smem + SB_OFF;
    int tid = threadIdx.x;
    int n0 = blockIdx.x * 128;
    int colbase = blockIdx.y * NB_COLS;

    for (int g = tid; g < NB_COLS * 4; g += 256) {
        int row = g >> 2, sub = g & 3;
        *(uint4*)(sB + row * 80 + sub * 16) =
            *(const uint4*)(g_Wh + (colbase + row) * 32 + sub * 8);
    }
    for (int g = tid; g < 512; g += 256) {
        int row = g >> 2, sub = g & 3;
        int n = n0 + row;
        uint4 hv = make_uint4(0, 0, 0, 0);
        if (n < N) {
            const float4* xp = (const float4*)(x + (size_t)n * 32 + sub * 8);
            float4 a = xp[0], b = xp[1];
            hv.x = packh2(a.x, a.y);
            hv.y = packh2(a.z, a.w);
            hv.z = packh2(b.x, b.y);
            hv.w = packh2(b.z, b.w);
        }
        *(uint4*)(sA + row * 80 + sub * 16) = hv;
    }
    __syncthreads();

    int wid = tid >> 5, lane = tid & 31;
    int m0 = wid * 16;
    int r = lane & 7, sel = lane >> 3;

    uint32_t aaddr = smem_u32(sA + (m0 + r + ((sel & 1) ? 8 : 0)) * 80 + (sel >> 1) * 16);
    uint32_t a[8];
    ldsm_x4(aaddr,      a);
    ldsm_x4(aaddr + 32, a + 4);

    uint32_t sBu  = smem_u32(sB);
    uint32_t bofs = (r + ((sel >> 1) ? 8 : 0)) * 80 + (sel & 1) * 16;

    int mrow  = lane >> 2;
    int ncol0 = (lane & 3) * 2;
    int node_lo = n0 + m0 + mrow;
    int node_hi = node_lo + 8;
    __half* z_lo = g_Zh + (size_t)node_lo * KM + colbase;
    __half* z_hi = g_Zh + (size_t)node_hi * KM + colbase;
    bool ok_lo = node_lo < N, ok_hi = node_hi < N;

    for (int nb = 0; nb < NB_COLS; nb += 16) {
        uint32_t baddr = sBu + nb * 80 + bofs;
        uint32_t b[8];
        ldsm_x4(baddr,      b);
        ldsm_x4(baddr + 32, b + 4);

        float acc0[4] = {0.f, 0.f, 0.f, 0.f};
        float acc1[4] = {0.f, 0.f, 0.f, 0.f};
        mma16816(acc0, a,     b[0], b[1]);
        mma16816(acc0, a + 4, b[4], b[5]);
        mma16816(acc1, a,     b[2], b[3]);
        mma16816(acc1, a + 4, b[6], b[7]);

        if (ok_lo) {
            *(uint32_t*)(z_lo + nb + ncol0)     = packh2(acc0[0], acc0[1]);
            *(uint32_t*)(z_lo + nb + 8 + ncol0) = packh2(acc1[0], acc1[1]);
        }
        if (ok_hi) {
            *(uint32_t*)(z_hi + nb + ncol0)     = packh2(acc0[2], acc0[3]);
            *(uint32_t*)(z_hi + nb + 8 + ncol0) = packh2(acc1[2], acc1[3]);
        }
    }
}

// ---------------- fused CSR edge + finalize: warp/node, 4 edges per instruction ----------------
// Quarter q (lanes 8q..8q+7) processes its own edges; lane ql = lane&7 handles
// channels {4ql..4ql+3} as uint2 (2x half2). Tap load: 8 lanes x 8B = one 64B row.
// Merge via shfl_xor(8), shfl_xor(16); redistribute with 4 shuffles.
__global__ __launch_bounds__(256)
void k_edge_csr(const float* __restrict__ x, const float* __restrict__ rootw,
                const float* __restrict__ bias, float* __restrict__ out, int N) {
    __shared__ float sR[1024];
    __shared__ float sB[32];
    int tid = threadIdx.x;
    for (int i = tid; i < 1024; i += 256) sR[i] = rootw[i];
    if (tid < 32) sB[tid] = bias[tid];
    __syncthreads();

    int lane = tid & 31, wid = tid >> 5;
    int n = blockIdx.x * 8 + wid;
    if (n >= N) return;

    int q  = lane >> 3;          // quarter id (edge slot)
    int ql = lane & 7;           // sub-lane: channels 4ql..4ql+3

    int s   = g_startN[n];
    int e2  = g_startN[n + 1];
    int deg = e2 - s;
    const float inv16 = 1.0f / 65535.0f;

    float a0 = 0.f, a1 = 0.f, a2 = 0.f, a3 = 0.f;
    int niter = (deg + 15) >> 4;         // 16 edges per iteration (4 per quarter)
    for (int it = 0; it < niter; it++) {
        int qb = s + it * 16 + q * 4;
        uint2 dd[4];
#pragma unroll
        for (int j = 0; j < 4; j++) {
            int e = qb + j; if (e > e2 - 1) e = e2 - 1;
            dd[j] = g_edesc2[e];
        }
        uint2 t0[4], t1[4], t2[4], t3[4];
#pragma unroll
        for (int j = 0; j < 4; j++) {
            const __half* zb = g_Zh + (size_t)(dd[j].x & 0xFFFFFu) * KM
                             + ((dd[j].x >> 20) << 5) + 4 * ql;
            t0[j] = *(const uint2*)(zb);          // tap (ix  , iy  ): 4 channels
            t1[j] = *(const uint2*)(zb + 32);     // tap (ix+1, iy  )
            t2[j] = *(const uint2*)(zb + 160);    // tap (ix  , iy+1)
            t3[j] = *(const uint2*)(zb + 192);    // tap (ix+1, iy+1)
        }
#pragma unroll
        for (int j = 0; j < 4; j++) {
            if (qb + j < e2) {
                float fx = (float)(dd[j].y & 0xFFFFu) * inv16;
                float fy = (float)(dd[j].y >> 16)     * inv16;
                float w00 = (1.0f - fx) * (1.0f - fy);
                float w10 = fx * (1.0f - fy);
                float w01 = (1.0f - fx) * fy;
                float w11 = fx * fy;
                float2 u0a = __half22float2(*(__half2*)&t0[j].x);
                float2 u0b = __half22float2(*(__half2*)&t0[j].y);
                float2 u1a = __half22float2(*(__half2*)&t1[j].x);
                float2 u1b = __half22float2(*(__half2*)&t1[j].y);
                float2 u2a = __half22float2(*(__half2*)&t2[j].x);
                float2 u2b = __half22float2(*(__half2*)&t2[j].y);
                float2 u3a = __half22float2(*(__half2*)&t3[j].x);
                float2 u3b = __half22float2(*(__half2*)&t3[j].y);
                a0 += w00 * u0a.x + w10 * u1a.x + w01 * u2a.x + w11 * u3a.x;
                a1 += w00 * u0a.y + w10 * u1a.y + w01 * u2a.y + w11 * u3a.y;
                a2 += w00 * u0b.x + w10 * u1b.x + w01 * u2b.x + w11 * u3b.x;
                a3 += w00 * u0b.y + w10 * u1b.y + w01 * u2b.y + w11 * u3b.y;
            }
        }
    }
    // merge quarters (all quarters share the same channel mapping)
    a0 += __shfl_xor_sync(0xffffffffu, a0, 8);
    a0 += __shfl_xor_sync(0xffffffffu, a0, 16);
    a1 += __shfl_xor_sync(0xffffffffu, a1, 8);
    a1 += __shfl_xor_sync(0xffffffffu, a1, 16);
    a2 += __shfl_xor_sync(0xffffffffu, a2, 8);
    a2 += __shfl_xor_sync(0xffffffffu, a2, 16);
    a3 += __shfl_xor_sync(0xffffffffu, a3, 8);
    a3 += __shfl_xor_sync(0xffffffffu, a3, 16);

    // redistribute: lane c needs channel c = 4*(c>>2) + (c&3), held in lane c>>2
    int src = lane >> 2;
    float v0 = __shfl_sync(0xffffffffu, a0, src);
    float v1 = __shfl_sync(0xffffffffu, a1, src);
    float v2 = __shfl_sync(0xffffffffu, a2, src);
    float v3 = __shfl_sync(0xffffffffu, a3, src);
    int m = lane & 3;
    float lo = (m & 1) ? v1 : v0;
    float hi = (m & 1) ? v3 : v2;
    float aval = (m & 2) ? hi : lo;

    // finalize: mean + root term + bias
    float xv = x[(size_t)n * 32 + lane];
    float rt = 0.0f;
#pragma unroll
    for (int i = 0; i < 32; i++) {
        float xi = __shfl_sync(0xffffffffu, xv, i);
        rt += xi * sR[i * 32 + lane];
    }
    float degf = fmaxf((float)deg, 1.0f);
    out[(size_t)n * 32 + lane] = aval / degf + rt + sB[lane];
}

// ---------------- launch ----------------
extern "C" void kernel_launch(void* const* d_in, const int* in_sizes, int n_in,
                              void* d_out, int out_size) {
    const float* x      = (const float*)d_in[0];
    const void*  ei     = d_in[1];
    const float* pseudo = (const float*)d_in[2];
    const float* weight = (const float*)d_in[3];
    const float* rootw  = (const float*)d_in[4];
    const float* bias   = (const float*)d_in[5];
    float*       out    = (float*)d_out;

    int N  = in_sizes[0] / 32;
    int E  = in_sizes[2] / 2;
    int N1 = N + 1;
    int nsb = (N1 + 1023) / 1024;

    k_detect<<<1, 256>>>((const unsigned int*)ei, 2 * E);
    k_zeroh<<<(N1 + 255) / 256, 256>>>(N1);
    k_hist<<<(E + 255) / 256, 256>>>(ei, E);
    kA_bsum<<<nsb, 1024>>>(N1);
    kB_scan<<<1, 256>>>(nsb);
    kC_scan<<<nsb, 1024>>>(N1);
    k_scatter<<<(E + 255) / 256, 256>>>(ei, pseudo, E);

    k_prep<<<(KTOT * 1024 + 255) / 256, 256>>>(weight);
    cudaFuncSetAttribute(k_zgemm_mma, cudaFuncAttributeMaxDynamicSharedMemorySize, ZG_SMEM);
    dim3 zg((N + 127) / 128, 2);
    k_zgemm_mma<<<zg, 256, ZG_SMEM>>>(x, N);

    k_edge_csr<<<(N + 7) / 8, 256>>>(x, rootw, bias, out, N);
}

// round 14
// speedup vs baseline: 1.1176x; 1.1176x over previous
#include <cuda_runtime.h>
#include <cuda_fp16.h>
#include <stdint.h>

// SplineConv: N=100000, E=1.6M, DIM=2, K=5, deg-1 open spline, M_in=M_out=32, K_TOT=25.
#define MAXN 100000
#define MAXE 1600000
#define KTOT 25
#define KM   800    // KTOT*32 Z-channels per node

// ---------------- device scratch (allocation-free) ----------------
__device__ __half g_Zh[(size_t)MAXN * KM];   // 160 MB fp16 Z[n, p]  (p = k*32+o)
__device__ __half g_Wh[KTOT * 32 * 32];      // [p=800][i=32] f16  (B operand)
__device__ uint2  g_edesc2[MAXE];            // row-sorted 8B descriptors {col|kidx<<20, fx16|fy16<<16}
__device__ int    g_histN[MAXN + 1];
__device__ int    g_startN[MAXN + 1];        // CSR offsets
__device__ int    g_offN[MAXN + 1];          // scatter cursors
__device__ int    g_bsum[256];
__device__ int    g_bpre[256];
__device__ int    g_is64;

__device__ __forceinline__ uint32_t smem_u32(const void* p) {
    uint32_t a;
    asm("{ .reg .u64 t; cvta.to.shared.u64 t, %1; cvt.u32.u64 %0, t; }" : "=r"(a) : "l"(p));
    return a;
}
__device__ __forceinline__ void ldsm_x4(uint32_t addr, uint32_t* r) {
    asm volatile("ldmatrix.sync.aligned.m8n8.x4.shared.b16 {%0,%1,%2,%3}, [%4];"
        : "=r"(r[0]), "=r"(r[1]), "=r"(r[2]), "=r"(r[3]) : "r"(addr));
}
__device__ __forceinline__ void mma16816(float* d, const uint32_t* a, uint32_t b0, uint32_t b1) {
    asm volatile("mma.sync.aligned.m16n8k16.row.col.f32.f16.f16.f32 "
        "{%0,%1,%2,%3}, {%4,%5,%6,%7}, {%8,%9}, {%0,%1,%2,%3};"
        : "+f"(d[0]), "+f"(d[1]), "+f"(d[2]), "+f"(d[3])
        : "r"(a[0]), "r"(a[1]), "r"(a[2]), "r"(a[3]), "r"(b0), "r"(b1));
}
__device__ __forceinline__ uint32_t packh2(float lo, float hi) {
    uint32_t r;
    asm("cvt.rn.f16x2.f32 %0, %1, %2;" : "=r"(r) : "f"(hi), "f"(lo));
    return r;
}

// ---------------- dtype detection + histogram zero ----------------
__global__ void k_detect(const unsigned int* __restrict__ w, int nwords) {
    __shared__ int nz;
    if (threadIdx.x == 0) nz = 0;
    __syncthreads();
    int lim = nwords < 4096 ? nwords : 4096;
    int any = 0;
    for (int i = 1 + 2 * (int)threadIdx.x; i < lim; i += 2 * (int)blockDim.x)
        if (w[i] != 0u) any = 1;
    if (any) atomicOr(&nz, 1);
    __syncthreads();
    if (threadIdx.x == 0) g_is64 = (nz == 0) ? 1 : 0;
}

__global__ void k_zeroh(int N1) {
    int i = blockIdx.x * blockDim.x + threadIdx.x;
    if (i < N1) g_histN[i] = 0;
}

// ---------------- per-node degree histogram (100k spread atomics) ----------------
__global__ __launch_bounds__(256)
void k_hist(const void* __restrict__ ei, int E) {
    int e = blockIdx.x * blockDim.x + threadIdx.x;
    if (e >= E) return;
    int r;
    if (g_is64) r = (int)((const long long*)ei)[e];
    else        r = ((const int*)ei)[e];
    atomicAdd(&g_histN[r], 1);
}

// ---------------- multi-block scan (A: block sums, B: scan sums, C: local scan) ----------------
__global__ void kA_bsum(int N1) {
    __shared__ int ws[32];
    int t = threadIdx.x;
    int i = blockIdx.x * 1024 + t;
    int v = (i < N1) ? g_histN[i] : 0;
    for (int o = 16; o > 0; o >>= 1) v += __shfl_down_sync(0xffffffffu, v, o);
    if ((t & 31) == 0) ws[t >> 5] = v;
    __syncthreads();
    if (t < 32) {
        int s = ws[t];
        for (int o = 16; o > 0; o >>= 1) s += __shfl_down_sync(0xffffffffu, s, o);
        if (t == 0) g_bsum[blockIdx.x] = s;
    }
}
__global__ void kB_scan(int nsb) {
    __shared__ int ws[8];
    int t = threadIdx.x;
    int v = (t < nsb) ? g_bsum[t] : 0;
    int lane = t & 31, wid = t >> 5;
    int s = v;
    for (int o = 1; o < 32; o <<= 1) {
        int u = __shfl_up_sync(0xffffffffu, s, o);
        if (lane >= o) s += u;
    }
    if (lane == 31) ws[wid] = s;
    __syncthreads();
    if (wid == 0 && lane < 8) {
        int x2 = ws[lane];
        for (int o = 1; o < 8; o <<= 1) {
            int u = __shfl_up_sync(0xffu, x2, o);
            if (lane >= o) x2 += u;
        }
        ws[lane] = x2;
    }
    __syncthreads();
    int incl = s + (wid > 0 ? ws[wid - 1] : 0);
    if (t < nsb) g_bpre[t] = incl - v;
}
__global__ void kC_scan(int N1) {
    __shared__ int ws[32];
    int t = threadIdx.x;
    int i = blockIdx.x * 1024 + t;
    int v = (i < N1) ? g_histN[i] : 0;
    int lane = t & 31, wid = t >> 5;
    int s = v;
    for (int o = 1; o < 32; o <<= 1) {
        int u = __shfl_up_sync(0xffffffffu, s, o);
        if (lane >= o) s += u;
    }
    if (lane == 31) ws[wid] = s;
    __syncthreads();
    if (wid == 0) {
        int x2 = ws[lane];
        for (int o = 1; o < 32; o <<= 1) {
            int u = __shfl_up_sync(0xffffffffu, x2, o);
            if (lane >= o) x2 += u;
        }
        ws[lane] = x2;
    }
    __syncthreads();
    int excl = s - v + (wid > 0 ? ws[wid - 1] : 0) + g_bpre[blockIdx.x];
    if (i < N1) { g_startN[i] = excl; g_offN[i] = excl; }
}

// ---------------- scatter: compute 8B descriptor, counting-sort by row ----------------
__global__ __launch_bounds__(256)
void k_scatter(const void* __restrict__ ei, const float* __restrict__ pseudo, int E) {
    int e = blockIdx.x * blockDim.x + threadIdx.x;
    if (e >= E) return;
    int r, c;
    if (g_is64) {
        const long long* p = (const long long*)ei;
        r = (int)p[e]; c = (int)p[(size_t)E + e];
    } else {
        const int* p = (const int*)ei;
        r = p[e]; c = p[E + e];
    }
    float2 ps = ((const float2*)pseudo)[e];
    float px = ps.x * 4.0f, py = ps.y * 4.0f;   // scale = K-1 (open spline)
    float lx = fminf(fmaxf(floorf(px), 0.0f), 3.0f);
    float ly = fminf(fmaxf(floorf(py), 0.0f), 3.0f);
    int kidx = (int)ly * 5 + (int)lx;           // 0..18
    uint32_t fxu = (uint32_t)((px - lx) * 65535.0f + 0.5f);
    uint32_t fyu = (uint32_t)((py - ly) * 65535.0f + 0.5f);
    int pos = atomicAdd(&g_offN[r], 1);         // 100k spread cursors
    g_edesc2[pos] = make_uint2((uint32_t)c | ((uint32_t)kidx << 20),
                               fxu | (fyu << 16));
}

// ---------------- W transpose+convert: g_Wh[p][i] = W[k,i,o], p=k*32+o ----------------
__global__ void k_prep(const float* __restrict__ w) {
    int t = blockIdx.x * blockDim.x + threadIdx.x;
    if (t >= KTOT * 1024) return;
    int p = t >> 5, i = t & 31;
    int k = p >> 5, o = p & 31;
    g_Wh[t] = __float2half(w[k * 1024 + i * 32 + o]);
}

// ---------------- Z = x @ Wt via mma.sync m16n8k16, split-N, coalesced stores ----------------
#define NB_COLS 400
#define SB_OFF  10240                     // A: 128*80
#define SW_OFF  (10240 + NB_COLS * 80)    // B end: 42240
#define ZG_SMEM (SW_OFF + 8 * 512)        // + per-warp 512B bounce tiles = 46336

__global__ __launch_bounds__(256, 4)
void k_zgemm_mma(const float* __restrict__ x, int N) {
    extern __shared__ __align__(128) char smem[];
    char* sA = smem;
    char* sB = smem + SB_OFF;
    int tid = threadIdx.x;
    int n0 = blockIdx.x * 128;
    int colbase = blockIdx.y * NB_COLS;

    for (int g = tid; g < NB_COLS * 4; g += 256) {
        int row = g >> 2, sub = g & 3;
        *(uint4*)(sB + row * 80 + sub * 16) =
            *(const uint4*)(g_Wh + (colbase + row) * 32 + sub * 8);
    }
    for (int g = tid; g < 512; g += 256) {
        int row = g >> 2, sub = g & 3;
        int n = n0 + row;
        uint4 hv = make_uint4(0, 0, 0, 0);
        if (n < N) {
            const float4* xp = (const float4*)(x + (size_t)n * 32 + sub * 8);
            float4 a = xp[0], b = xp[1];
            hv.x = packh2(a.x, a.y);
            hv.y = packh2(a.z, a.w);
            hv.z = packh2(b.x, b.y);
            hv.w = packh2(b.z, b.w);
        }
        *(uint4*)(sA + row * 80 + sub * 16) = hv;
    }
    __syncthreads();

    int wid = tid >> 5, lane = tid & 31;
    int m0 = wid * 16;
    int r = lane & 7, sel = lane >> 3;

    uint32_t aaddr = smem_u32(sA + (m0 + r + ((sel & 1) ? 8 : 0)) * 80 + (sel >> 1) * 16);
    uint32_t a[8];
    ldsm_x4(aaddr,      a);
    ldsm_x4(aaddr + 32, a + 4);

    uint32_t sBu  = smem_u32(sB);
    uint32_t bofs = (r + ((sel >> 1) ? 8 : 0)) * 80 + (sel & 1) * 16;

    int mrow  = lane >> 2;          // 0..7
    int ncol0 = (lane & 3) * 2;
    char* sw  = smem + SW_OFF + wid * 512;   // 16 rows x 32B bounce tile
    int srow  = lane >> 1, shalf = lane & 1; // store mapping
    int snode = n0 + m0 + srow;
    bool sok  = snode < N;
    __half* zrow = g_Zh + (size_t)snode * KM + colbase;

    for (int nb = 0; nb < NB_COLS; nb += 16) {
        uint32_t baddr = sBu + nb * 80 + bofs;
        uint32_t b[8];
        ldsm_x4(baddr,      b);
        ldsm_x4(baddr + 32, b + 4);

        float acc0[4] = {0.f, 0.f, 0.f, 0.f};
        float acc1[4] = {0.f, 0.f, 0.f, 0.f};
        mma16816(acc0, a,     b[0], b[1]);
        mma16816(acc0, a + 4, b[4], b[5]);
        mma16816(acc1, a,     b[2], b[3]);
        mma16816(acc1, a + 4, b[6], b[7]);

        // bounce 16x16 f16 tile through smem for full-sector global stores
        *(uint32_t*)(sw + mrow * 32 + ncol0 * 2)             = packh2(acc0[0], acc0[1]);
        *(uint32_t*)(sw + mrow * 32 + (ncol0 + 8) * 2)       = packh2(acc1[0], acc1[1]);
        *(uint32_t*)(sw + (mrow + 8) * 32 + ncol0 * 2)       = packh2(acc0[2], acc0[3]);
        *(uint32_t*)(sw + (mrow + 8) * 32 + (ncol0 + 8) * 2) = packh2(acc1[2], acc1[3]);
        __syncwarp();
        if (sok) {
            uint4 v = *(uint4*)(sw + srow * 32 + shalf * 16);
            *(uint4*)(zrow + nb + shalf * 8) = v;   // 32B/row full sectors
        }
        __syncwarp();
    }
}

// ---------------- fused CSR edge + finalize: warp/node, half-warp edge packing ----------------
// Half-warp h (lanes 16h..16h+15) processes its own edges; lane sl handles
// channels {2sl, 2sl+1} as half2. Invalid tail slots load 0 (contribute 0).
__global__ __launch_bounds__(256)
void k_edge_csr(const float* __restrict__ x, const float* __restrict__ rootw,
                const float* __restrict__ bias, float* __restrict__ out, int N) {
    __shared__ float sR[1024];
    __shared__ float sB[32];
    int tid = threadIdx.x;
    for (int i = tid; i < 1024; i += 256) sR[i] = rootw[i];
    if (tid < 32) sB[tid] = bias[tid];
    __syncthreads();

    int lane = tid & 31, wid = tid >> 5;
    int n = blockIdx.x * 8 + wid;
    if (n >= N) return;

    int h  = lane >> 4;          // half-warp id (edge slot)
    int sl = lane & 15;          // sub-lane: channels 2sl, 2sl+1

    int s   = g_startN[n];
    int e2  = g_startN[n + 1];
    int deg = e2 - s;
    const float inv16 = 1.0f / 65535.0f;

    float accx = 0.0f, accy = 0.0f;
    int niter = (deg + 7) >> 3;          // 8 edges per iteration (4 per half)
    for (int it = 0; it < niter; it++) {
        int qb = s + it * 8 + h * 4;
        uint2 dd[4];
#pragma unroll
        for (int j = 0; j < 4; j++) {
            int e = qb + j; if (e > e2 - 1) e = e2 - 1;
            dd[j] = g_edesc2[e];
        }
        uint32_t t0[4], t1[4], t2[4], t3[4];
#pragma unroll
        for (int j = 0; j < 4; j++) {
            if (qb + j < e2) {
                const __half* zb = g_Zh + (size_t)(dd[j].x & 0xFFFFFu) * KM
                                 + ((dd[j].x >> 20) << 5) + 2 * sl;
                t0[j] = *(const uint32_t*)(zb);        // taps: 2 channels each
                t1[j] = *(const uint32_t*)(zb + 32);
                t2[j] = *(const uint32_t*)(zb + 160);
                t3[j] = *(const uint32_t*)(zb + 192);
            } else {
                t0[j] = 0u; t1[j] = 0u; t2[j] = 0u; t3[j] = 0u;
            }
        }
#pragma unroll
        for (int j = 0; j < 4; j++) {
            // invalid slots have zero taps -> contribute exactly 0 (no guard needed)
            float fx = (float)(dd[j].y & 0xFFFFu) * inv16;
            float fy = (float)(dd[j].y >> 16)     * inv16;
            float w00 = (1.0f - fx) * (1.0f - fy);
            float w10 = fx * (1.0f - fy);
            float w01 = (1.0f - fx) * fy;
            float w11 = fx * fy;
            float2 z0 = __half22float2(*(__half2*)&t0[j]);
            float2 z1 = __half22float2(*(__half2*)&t1[j]);
            float2 z2 = __half22float2(*(__half2*)&t2[j]);
            float2 z3 = __half22float2(*(__half2*)&t3[j]);
            accx += w00 * z0.x + w10 * z1.x + w01 * z2.x + w11 * z3.x;
            accy += w00 * z0.y + w10 * z1.y + w01 * z2.y + w11 * z3.y;
        }
    }
    // merge the two half-warps (same channel mapping)
    accx += __shfl_xor_sync(0xffffffffu, accx, 16);
    accy += __shfl_xor_sync(0xffffffffu, accy, 16);

    // redistribute: lane c needs channel c (held in lane c>>1 as .x/.y)
    float ax = __shfl_sync(0xffffffffu, accx, lane >> 1);
    float ay = __shfl_sync(0xffffffffu, accy, lane >> 1);
    float aval = (lane & 1) ? ay : ax;

    // finalize: mean + root term + bias
    float xv = x[(size_t)n * 32 + lane];
    float rt = 0.0f;
#pragma unroll
    for (int i = 0; i < 32; i++) {
        float xi = __shfl_sync(0xffffffffu, xv, i);
        rt += xi * sR[i * 32 + lane];
    }
    float degf = fmaxf((float)deg, 1.0f);
    out[(size_t)n * 32 + lane] = aval / degf + rt + sB[lane];
}

// ---------------- launch ----------------
extern "C" void kernel_launch(void* const* d_in, const int* in_sizes, int n_in,
                              void* d_out, int out_size) {
    const float* x      = (const float*)d_in[0];
    const void*  ei     = d_in[1];
    const float* pseudo = (const float*)d_in[2];
    const float* weight = (const float*)d_in[3];
    const float* rootw  = (const float*)d_in[4];
    const float* bias   = (const float*)d_in[5];
    float*       out    = (float*)d_out;

    int N  = in_sizes[0] / 32;
    int E  = in_sizes[2] / 2;
    int N1 = N + 1;
    int nsb = (N1 + 1023) / 1024;

    k_detect<<<1, 256>>>((const unsigned int*)ei, 2 * E);
    k_zeroh<<<(N1 + 255) / 256, 256>>>(N1);
    k_hist<<<(E + 255) / 256, 256>>>(ei, E);
    kA_bsum<<<nsb, 1024>>>(N1);
    kB_scan<<<1, 256>>>(nsb);
    kC_scan<<<nsb, 1024>>>(N1);
    k_scatter<<<(E + 255) / 256, 256>>>(ei, pseudo, E);

    k_prep<<<(KTOT * 1024 + 255) / 256, 256>>>(weight);
    cudaFuncSetAttribute(k_zgemm_mma, cudaFuncAttributeMaxDynamicSharedMemorySize, ZG_SMEM);
    dim3 zg((N + 127) / 128, 2);
    k_zgemm_mma<<<zg, 256, ZG_SMEM>>>(x, N);

    k_edge_csr<<<(N + 7) / 8, 256>>>(x, rootw, bias, out, N);
}